// round 16
// baseline (speedup 1.0000x reference)
#include <cuda_runtime.h>
#include <cuda_fp16.h>
#include <cstdint>

#define NB 256
#define ND 512
#define NL 64
#define NH 300
#define CM 64                 // batch rows per decoder CTA

// strides (bytes) for k-major SMEM operands
#define STR1 144              // k=64 padded to 72 halves
#define STR2 624              // k=304 padded to 312 halves

// ---- decoder SMEM layout (bytes) ------------------------------------------
#define OFF_G1    0                        // g1 fp16 [64][312h] = 39936
#define OFF_MHI   39936                    // masked hi 64*144 = 9216 (XCH later)
#define OFF_MLO   49152                    // masked lo 9216
#define OFF_XCH   OFF_MHI                  // split-k exchange (10240 B, GEMM2 only)
#define OFF_B     58368                    // two ping-pong buffers
#define BUFSZ     24960                    // B1 piece 23040 / B2 piece 24960
#define OFF_HEAD  108288                   // 320 floats
#define OFF_BIAS  109568                   // 320 floats
#define OFF_XRED  110848                   // 128 floats
#define SMEM_TOTAL 111360

__device__ __align__(16) float g_zT[NL * NB];       // z transposed [l][b]
__device__ __align__(16) __half g_g1hi[320 * 64];   // gen1 hi, padded rows
__device__ __align__(16) __half g_g2hi[320 * 320];  // gen2 hi only

// ---------------- helpers --------------------------------------------------
static __device__ __forceinline__ uint32_t smem_u32(const void* p) {
    uint32_t a;
    asm("{ .reg .u64 t; cvta.to.shared.u64 t, %1; cvt.u32.u64 %0, t; }" : "=r"(a) : "l"(p));
    return a;
}
static __device__ __forceinline__ void ldsm_x4(uint32_t* r, uint32_t addr) {
    asm volatile("ldmatrix.sync.aligned.m8n8.x4.shared.b16 {%0,%1,%2,%3}, [%4];"
                 : "=r"(r[0]), "=r"(r[1]), "=r"(r[2]), "=r"(r[3]) : "r"(addr));
}
static __device__ __forceinline__ void ldsm_x2(uint32_t* r, uint32_t addr) {
    asm volatile("ldmatrix.sync.aligned.m8n8.x2.shared.b16 {%0,%1}, [%2];"
                 : "=r"(r[0]), "=r"(r[1]) : "r"(addr));
}
static __device__ __forceinline__ void mma_f16(float* c, const uint32_t* a, const uint32_t* b) {
    asm volatile("mma.sync.aligned.m16n8k16.row.col.f32.f16.f16.f32 "
                 "{%0,%1,%2,%3}, {%4,%5,%6,%7}, {%8,%9}, {%0,%1,%2,%3};"
                 : "+f"(c[0]), "+f"(c[1]), "+f"(c[2]), "+f"(c[3])
                 : "r"(a[0]), "r"(a[1]), "r"(a[2]), "r"(a[3]), "r"(b[0]), "r"(b[1]));
}
static __device__ __forceinline__ void cp16(uint32_t dst, const void* src) {
    asm volatile("cp.async.cg.shared.global [%0], [%1], 16;" :: "r"(dst), "l"(src) : "memory");
}
static __device__ __forceinline__ void cp_commit() { asm volatile("cp.async.commit_group;" ::: "memory"); }
static __device__ __forceinline__ void cp_wait0()  { asm volatile("cp.async.wait_group 0;" ::: "memory"); }
static __device__ __forceinline__ void cp_wait1()  { asm volatile("cp.async.wait_group 1;" ::: "memory"); }

static __device__ __forceinline__ void split_f16(float v, __half& h, __half& l) {
    h = __float2half_rn(v);
    l = __float2half_rn(v - __half2float(h));
}
static __device__ __forceinline__ uint32_t pack_relu2(float v0, float v1) {
    __half h0 = __float2half_rn(fmaxf(v0, 0.f));
    __half h1 = __float2half_rn(fmaxf(v1, 0.f));
    return (uint32_t)__half_as_ushort(h0) | ((uint32_t)__half_as_ushort(h1) << 16);
}

// ---------------------------------------------------------------------------
// Pre: blocks [0, 64) = encoder (4 batch rows per CTA, 640 threads = 2 groups
//      of 320, each group owns 2 rows -> half the serial dot length);
//      blocks [64, 224) = weight prep (gen1 hi padded, gen2 hi).
// ---------------------------------------------------------------------------
__global__ __launch_bounds__(640) void pre_kernel(
    const float* __restrict__ x, const float* __restrict__ eps,
    const float* __restrict__ enc1_w, const float* __restrict__ enc1_b,
    const float* __restrict__ enc2_w, const float* __restrict__ enc2_b,
    const float* __restrict__ zm_w, const float* __restrict__ zm_b,
    const float* __restrict__ zv_w, const float* __restrict__ zv_b,
    const float* __restrict__ g1w, const float* __restrict__ g2w,
    float* __restrict__ out)
{
    const int t = threadIdx.x;
    if (blockIdx.x >= 64) {
        int idx = (blockIdx.x - 64) * 640 + t;   // [0, 102400)
        {
            int r = idx / 320, c = idx - r * 320;
            float v = (r < NH && c < NH) ? g2w[r * NH + c] : 0.f;
            g_g2hi[idx] = __float2half_rn(v);
        }
        if (idx < 320 * 64) {
            int r = idx >> 6, c = idx & 63;
            float v = (r < NH) ? g1w[r * NL + c] : 0.f;
            g_g1hi[idx] = __float2half_rn(v);
        }
        return;
    }

    __shared__ float xs[4][ND];
    __shared__ float h1s[4][NH];
    __shared__ float h2s[4][NH];
    __shared__ float zms[4][NL];
    __shared__ float zvs[4][NL];

    const int b0 = blockIdx.x * 4;
    const int grp = t >= 320 ? 1 : 0;     // row group: rows {grp*2, grp*2+1}
    const int tt = t - grp * 320;

    for (int idx = t; idx < 4 * ND; idx += 640)
        xs[idx >> 9][idx & 511] = x[b0 * ND + idx];
    __syncthreads();

    if (tt < NH) {
        float acc0 = enc1_b[tt], acc1 = acc0;
        const float4* w4 = reinterpret_cast<const float4*>(enc1_w + tt * ND);
        const int r0 = grp * 2;
        #pragma unroll 4
        for (int k = 0; k < ND / 4; k++) {
            float4 w = w4[k];
            float4 x0 = reinterpret_cast<const float4*>(xs[r0])[k];
            float4 x1 = reinterpret_cast<const float4*>(xs[r0 + 1])[k];
            acc0 += w.x * x0.x + w.y * x0.y + w.z * x0.z + w.w * x0.w;
            acc1 += w.x * x1.x + w.y * x1.y + w.z * x1.z + w.w * x1.w;
        }
        h1s[r0][tt] = fmaxf(acc0, 0.f);
        h1s[r0 + 1][tt] = fmaxf(acc1, 0.f);
    }
    __syncthreads();

    if (tt < NH) {
        float acc0 = enc2_b[tt], acc1 = acc0;
        const float4* w4 = reinterpret_cast<const float4*>(enc2_w + tt * NH);
        const int r0 = grp * 2;
        #pragma unroll 4
        for (int k = 0; k < NH / 4; k++) {
            float4 w = w4[k];
            float4 h0 = reinterpret_cast<const float4*>(h1s[r0])[k];
            float4 h1v = reinterpret_cast<const float4*>(h1s[r0 + 1])[k];
            acc0 += w.x * h0.x + w.y * h0.y + w.z * h0.z + w.w * h0.w;
            acc1 += w.x * h1v.x + w.y * h1v.y + w.z * h1v.z + w.w * h1v.w;
        }
        h2s[r0][tt] = fmaxf(acc0, 0.f);
        h2s[r0 + 1][tt] = fmaxf(acc1, 0.f);
    }
    __syncthreads();

    float* oz = out + NB * ND;
    if (t < 512) {
        const int l = t & 63, sel = (t >> 6) & 1, rg = (t >> 7) & 1;
        const float* wbase = sel ? zv_w : zm_w;
        float ac0 = sel ? zv_b[l] : zm_b[l];
        float ac1 = ac0;
        const float4* w4 = reinterpret_cast<const float4*>(wbase + l * NH);
        const int r0 = rg * 2;
        #pragma unroll 3
        for (int k = 0; k < NH / 4; k++) {
            float4 w = w4[k];
            float4 h0 = reinterpret_cast<const float4*>(h2s[r0])[k];
            float4 h1v = reinterpret_cast<const float4*>(h2s[r0 + 1])[k];
            ac0 += w.x * h0.x + w.y * h0.y + w.z * h0.z + w.w * h0.w;
            ac1 += w.x * h1v.x + w.y * h1v.y + w.z * h1v.z + w.w * h1v.w;
        }
        if (sel) {
            zvs[r0][l] = ac0; zvs[r0 + 1][l] = ac1;
            oz[2 * NB * NL + (b0 + r0) * NL + l] = ac0;
            oz[2 * NB * NL + (b0 + r0 + 1) * NL + l] = ac1;
        } else {
            zms[r0][l] = ac0; zms[r0 + 1][l] = ac1;
            oz[NB * NL + (b0 + r0) * NL + l] = ac0;
            oz[NB * NL + (b0 + r0 + 1) * NL + l] = ac1;
        }
    }
    __syncthreads();
    if (t < 128) {
        const int l = t & 63, rg = t >> 6;
        #pragma unroll
        for (int rr = 0; rr < 2; rr++) {
            int r = rg * 2 + rr, b = b0 + r;
            float e = eps[b * NL + l];
            float z = zms[r][l] + e * expf(0.5f * zvs[r][l]);
            g_zT[l * NB + b] = z;
            oz[b * NL + l] = z;
        }
    }
}

// ---------------------------------------------------------------------------
// Decoder: one CTA = (one column d, 64 batch rows). 256 threads, 8 warps,
// 2 CTAs/SM. mw = warp&3 (16-row m-block), nh = warp>>2.
// GEMM1 (fp16 2-term): masked A hi/lo preloaded in 32 regs; gen1-hi B in
//   2 pieces of 160 h-cols (nh splits 80/80), paired ldsm_x4 B loads.
// GEMM2 (fp16 1-term) split-k (nh=0: ks 0-9, nh=1: ks 10-18), A in regs;
//   8 pieces of 40 g-cols; reducer role ALTERNATES per piece; both nh
//   groups accumulate xp, combined at the end.
// ---------------------------------------------------------------------------
__global__ __launch_bounds__(256, 2) void decoder_kernel(
    const float* __restrict__ Wmat, const float* __restrict__ gen2_b,
    const float* __restrict__ head_w, const float* __restrict__ head_b,
    float* __restrict__ out_x)
{
    extern __shared__ char sm[];
    const uint32_t sb = smem_u32(sm);
    const int tid = threadIdx.x, warp = tid >> 5, lane = tid & 31;
    const int mw = warp & 3, nh = warp >> 2;
    const int d = blockIdx.x, b0 = blockIdx.y * CM;

    float* head_s = (float*)(sm + OFF_HEAD);
    float* bias_s = (float*)(sm + OFF_BIAS);

    // ---- issue gen1 B pieces 0,1 (160 rows x 128B each) --------------------
    #pragma unroll
    for (int p0 = 0; p0 < 2; p0++) {
        const char* src = (const char*)(g_g1hi + p0 * 160 * 64);
        uint32_t bufb = sb + OFF_B + p0 * BUFSZ;
        for (int idx = tid; idx < 1280; idx += 256) {
            uint32_t doff = (uint32_t)((idx >> 3) * STR1 + (idx & 7) * 16);
            cp16(bufb + doff, src + idx * 16);
        }
        cp_commit();
    }

    // ---- head/bias + masked split while loads fly --------------------------
    for (int i = tid; i < 320; i += 256) {
        head_s[i] = (i < NH) ? head_w[d * NH + i] : 0.f;
        bias_s[i] = (i < NH) ? gen2_b[i] : 0.f;
    }
    for (int idx = tid; idx < CM * NL; idx += 256) {
        int m = idx & 63, l = idx >> 6;
        float v = g_zT[l * NB + b0 + m] * Wmat[d * NL + l];
        __half h, lo; split_f16(v, h, lo);
        *(__half*)(sm + OFF_MHI + m * STR1 + l * 2) = h;
        *(__half*)(sm + OFF_MLO + m * STR1 + l * 2) = lo;
    }
    __syncthreads();

    // ---- preload A1 (masked hi/lo) fragments: 8 ldsm_x4, 32 regs ----------
    const uint32_t a1base = sb + OFF_MHI + (mw * 16 + (lane & 15)) * STR1 + ((lane >> 4) & 1) * 16;
    uint32_t a1h[4][4], a1l[4][4];
    #pragma unroll
    for (int ks = 0; ks < 4; ks++) {
        ldsm_x4(a1h[ks], a1base + ks * 32);
        ldsm_x4(a1l[ks], a1base + (OFF_MLO - OFF_MHI) + ks * 32);
    }

    // ---- GEMM1: 2 pieces of 160 h-cols (2-term, A in regs) -----------------
    #pragma unroll 1
    for (int i = 0; i < 2; i++) {
        cp_wait1();
        __syncthreads();
        const uint32_t bufb = sb + OFF_B + (uint32_t)((i & 1) * BUFSZ);

        float acc[10][4];
        #pragma unroll
        for (int t = 0; t < 10; t++) { acc[t][0] = acc[t][1] = acc[t][2] = acc[t][3] = 0.f; }
        #pragma unroll
        for (int ks = 0; ks < 4; ks++) {
            #pragma unroll
            for (int tp = 0; tp < 5; tp++) {
                uint32_t b4[4];
                uint32_t bb = bufb + (uint32_t)((nh * 80 + tp * 16 + ((lane >> 4) & 1) * 8 + (lane & 7)) * STR1)
                            + ((lane >> 3) & 1) * 16 + ks * 32;
                ldsm_x4(b4, bb);
                mma_f16(acc[2 * tp],     a1h[ks], b4);     mma_f16(acc[2 * tp],     a1l[ks], b4);
                mma_f16(acc[2 * tp + 1], a1h[ks], b4 + 2); mma_f16(acc[2 * tp + 1], a1l[ks], b4 + 2);
            }
        }
        // ReLU + fp16 store of g1
        #pragma unroll
        for (int t = 0; t < 10; t++) {
            int col = i * 160 + nh * 80 + t * 8 + 2 * (lane & 3);
            if (col < 304) {
                int r0 = mw * 16 + (lane >> 2);
                *(uint32_t*)(sm + OFF_G1 + r0 * STR2 + col * 2) = pack_relu2(acc[t][0], acc[t][1]);
                *(uint32_t*)(sm + OFF_G1 + (r0 + 8) * STR2 + col * 2) = pack_relu2(acc[t][2], acc[t][3]);
            }
        }
        __syncthreads();   // buf consumed + g1 piece visible

        // prefetch gen2 piece i into this buffer
        for (int idx = tid; idx < 40 * 38; idx += 256) {
            int r = idx / 38, q = idx - r * 38;
            cp16(bufb + r * STR2 + q * 16,
                 (const char*)(g_g2hi + (i * 40 + r) * 320) + q * 16);
        }
        cp_commit();
    }

    // ---- load A2 (g1) fragments into registers: nh-split of ks -------------
    const uint32_t a2base = sb + OFF_G1 + (mw * 16 + (lane & 15)) * STR2 + ((lane >> 4) & 1) * 16;
    const int ksbase = nh * 10;
    uint32_t a2r[10][4];
    #pragma unroll
    for (int k = 0; k < 10; k++)
        if (ksbase + k < 19) ldsm_x4(a2r[k], a2base + (ksbase + k) * 32);

    // ---- GEMM2: 8 pieces of 40 g-cols (1-term, A in regs, split-k) ---------
    float xp0 = 0.f, xp1 = 0.f;
    #pragma unroll 1
    for (int j = 0; j < 8; j++) {
        if (j < 7) cp_wait1(); else cp_wait0();
        __syncthreads();
        const uint32_t bufb = sb + OFF_B + (uint32_t)((j & 1) * BUFSZ);

        float acc[5][4];
        #pragma unroll
        for (int t = 0; t < 5; t++) { acc[t][0] = acc[t][1] = acc[t][2] = acc[t][3] = 0.f; }
        #pragma unroll
        for (int k = 0; k < 10; k++) {
            if (ksbase + k < 19) {
                uint32_t b4[4], b2[2];
                #pragma unroll
                for (int tp = 0; tp < 2; tp++) {
                    uint32_t bb = bufb + (uint32_t)((tp * 16 + ((lane >> 4) & 1) * 8 + (lane & 7)) * STR2)
                                + ((lane >> 3) & 1) * 16 + (ksbase + k) * 32;
                    ldsm_x4(b4, bb);
                    mma_f16(acc[2 * tp],     a2r[k], b4);
                    mma_f16(acc[2 * tp + 1], a2r[k], b4 + 2);
                }
                uint32_t bb2 = bufb + (uint32_t)((32 + (lane & 7)) * STR2)
                             + ((lane >> 3) & 1) * 16 + (ksbase + k) * 32;
                ldsm_x2(b2, bb2);
                mma_f16(acc[4], a2r[k], b2);
            }
        }

        // split-k exchange; reducer role alternates per piece
        const int red = j & 1;             // nh that reduces this piece
        if (nh != red) {
            #pragma unroll
            for (int t = 0; t < 5; t++) {
                float4 v = make_float4(acc[t][0], acc[t][1], acc[t][2], acc[t][3]);
                *(float4*)(sm + OFF_XCH + (((mw * 32 + lane) * 5 + t) << 4)) = v;
            }
        }
        __syncthreads();

        if (nh == red) {
            #pragma unroll
            for (int t = 0; t < 5; t++) {
                float4 p = *(const float4*)(sm + OFF_XCH + (((mw * 32 + lane) * 5 + t) << 4));
                float s0 = acc[t][0] + p.x, s1 = acc[t][1] + p.y;
                float s2 = acc[t][2] + p.z, s3 = acc[t][3] + p.w;
                int g = j * 40 + t * 8 + 2 * (lane & 3);
                float bb0 = bias_s[g], bb1 = bias_s[g + 1];
                float hh0 = head_s[g], hh1 = head_s[g + 1];
                xp0 = fmaf(fmaxf(s0 + bb0, 0.f), hh0, xp0);
                xp0 = fmaf(fmaxf(s1 + bb1, 0.f), hh1, xp0);
                xp1 = fmaf(fmaxf(s2 + bb0, 0.f), hh0, xp1);
                xp1 = fmaf(fmaxf(s3 + bb1, 0.f), hh1, xp1);
            }
        }

        if (j + 2 < 8) {
            for (int idx = tid; idx < 40 * 38; idx += 256) {
                int r = idx / 38, q = idx - r * 38;
                cp16(bufb + r * STR2 + q * 16,
                     (const char*)(g_g2hi + ((j + 2) * 40 + r) * 320) + q * 16);
            }
            cp_commit();
        }
    }

    // combine both nh groups' xp via SMEM (each reduced 4 of 8 pieces)
    xp0 += __shfl_xor_sync(0xFFFFFFFFu, xp0, 1);
    xp0 += __shfl_xor_sync(0xFFFFFFFFu, xp0, 2);
    xp1 += __shfl_xor_sync(0xFFFFFFFFu, xp1, 1);
    xp1 += __shfl_xor_sync(0xFFFFFFFFu, xp1, 2);

    float* xr = (float*)(sm + OFF_XRED);   // [2 nh][64 rows]
    __syncthreads();
    if ((lane & 3) == 0) {
        int r0 = mw * 16 + (lane >> 2);
        xr[nh * 64 + r0] = xp0;
        xr[nh * 64 + r0 + 8] = xp1;
    }
    __syncthreads();
    if (tid < CM)
        out_x[(b0 + tid) * ND + d] = xr[tid] + xr[64 + tid] + head_b[d];
}

extern "C" void kernel_launch(void* const* d_in, const int* in_sizes, int n_in,
                              void* d_out, int out_size)
{
    const float* x      = (const float*)d_in[0];
    const float* eps    = (const float*)d_in[1];
    const float* Wmat   = (const float*)d_in[2];
    const float* enc1_w = (const float*)d_in[3];
    const float* enc1_b = (const float*)d_in[4];
    const float* enc2_w = (const float*)d_in[5];
    const float* enc2_b = (const float*)d_in[6];
    const float* zm_w   = (const float*)d_in[7];
    const float* zm_b   = (const float*)d_in[8];
    const float* zv_w   = (const float*)d_in[9];
    const float* zv_b   = (const float*)d_in[10];
    const float* gen1_w = (const float*)d_in[11];
    const float* gen2_w = (const float*)d_in[12];
    const float* gen2_b = (const float*)d_in[13];
    const float* head_w = (const float*)d_in[14];
    const float* head_b = (const float*)d_in[15];
    float* out = (float*)d_out;

    static bool attr_set = false;
    if (!attr_set) {
        cudaFuncSetAttribute(decoder_kernel,
                             cudaFuncAttributeMaxDynamicSharedMemorySize, SMEM_TOTAL);
        attr_set = true;
    }

    pre_kernel<<<224, 640>>>(x, eps, enc1_w, enc1_b, enc2_w, enc2_b,
                             zm_w, zm_b, zv_w, zv_b, gen1_w, gen2_w, out);
    decoder_kernel<<<dim3(ND, NB / CM), 256, SMEM_TOTAL>>>(
        Wmat, gen2_b, head_w, head_b, out);
}